// round 1
// baseline (speedup 1.0000x reference)
#include <cuda_runtime.h>
#include <cuda_bf16.h>

// ---------------------------------------------------------------------------
// GraphSAGE 2-layer, fp32 baseline.
// Problem dims (fixed by the dataset):
//   N_SRC0=100000, N_DST0=20000, N_DST1=5000, E0=160000, E1=40000
//   IN_F=512, H_F=1024, N_CLS=256
// Pipeline:
//   zero scratch
//   layer1: deg0/scatter-sum over e0  -> normalize -> GEMM1 (concat) + ReLU -> h1
//   layer2: deg1/scatter-sum over e1  -> normalize -> GEMM2 (concat)        -> out
// ---------------------------------------------------------------------------

#define N_SRC0 100000
#define N_DST0 20000
#define N_DST1 5000
#define E0     160000
#define E1     40000
#define IN_F   512
#define H_F    1024
#define N_CLS  256

// Scratch (device globals; allocation is forbidden)
__device__ float g_sum1[(size_t)N_DST0 * IN_F];   // 40 MB
__device__ float g_deg0[N_DST0];
__device__ float g_h1[(size_t)N_DST0 * H_F];      // 80 MB
__device__ float g_sum2[(size_t)N_DST1 * H_F];    // 20 MB
__device__ float g_deg1[N_DST1];

// ---------------------------------------------------------------------------
__global__ void zero_kernel(float* p, long n) {
    long i = (long)blockIdx.x * blockDim.x + threadIdx.x;
    long stride = (long)gridDim.x * blockDim.x;
    for (; i < n; i += stride) p[i] = 0.0f;
}

// one thread per edge: deg[dst] += 1
__global__ void deg_kernel(const int* __restrict__ dst, float* __restrict__ deg, int E) {
    int e = blockIdx.x * blockDim.x + threadIdx.x;
    if (e < E) atomicAdd(&deg[dst[e]], 1.0f);
}

// thread = (edge, 4-col group): out[dst] += feat[src]
__global__ void scatter_kernel(const float* __restrict__ feat,
                               const int* __restrict__ src,
                               const int* __restrict__ dst,
                               float* __restrict__ out,
                               int E, int F) {
    int per = F >> 2;  // float4 groups per row
    long idx = (long)blockIdx.x * blockDim.x + threadIdx.x;
    if (idx >= (long)E * per) return;
    int e = (int)(idx / per);
    int c = (int)(idx % per) << 2;
    int s = src[e], d = dst[e];
    float4 v = *(const float4*)(feat + (long)s * F + c);
    float* o = out + (long)d * F + c;
    atomicAdd(o + 0, v.x);
    atomicAdd(o + 1, v.y);
    atomicAdd(o + 2, v.z);
    atomicAdd(o + 3, v.w);
}

// summed[row, :] *= 1 / max(deg[row], 1)
__global__ void normalize_kernel(float* __restrict__ sum,
                                 const float* __restrict__ deg,
                                 int n, int F) {
    long idx = (long)blockIdx.x * blockDim.x + threadIdx.x;
    long total = (long)n * (F >> 2);
    if (idx >= total) return;
    int per = F >> 2;
    int row = (int)(idx / per);
    int c = (int)(idx % per) << 2;
    float d = deg[row];
    float inv = 1.0f / fmaxf(d, 1.0f);
    float4* p = (float4*)(sum + (long)row * F + c);
    float4 v = *p;
    v.x *= inv; v.y *= inv; v.z *= inv; v.w *= inv;
    *p = v;
}

// ---------------------------------------------------------------------------
// SGEMM with virtual K-concat:
//   C[M,N] = A1[M,K] @ B1[K,N] + A2[M,K] @ B2[K,N] + bias  (optional ReLU)
// BM=BN=128, BK=8, 256 threads, 8x8 microtile per thread.
// ---------------------------------------------------------------------------
template <bool RELU>
__global__ __launch_bounds__(256, 2)
void sgemm_concat(const float* __restrict__ A1, const float* __restrict__ A2,
                  const float* __restrict__ B1, const float* __restrict__ B2,
                  const float* __restrict__ bias, float* __restrict__ C,
                  int M, int N, int K) {
    __shared__ float As[8][128];
    __shared__ float Bs[8][132];  // +4 pad to soften bank conflicts

    const int tid = threadIdx.x;
    const int m0 = blockIdx.y * 128;
    const int n0 = blockIdx.x * 128;

    // A-tile load mapping: 128 rows x 8 k; each thread loads one float4 (row, 4k)
    const int aRow = tid >> 1;          // 0..127
    const int aCol = (tid & 1) << 2;    // 0 or 4
    // B-tile load mapping: 8 k x 128 n; each thread loads one float4
    const int bRow = tid >> 5;          // 0..7
    const int bCol = (tid & 31) << 2;   // 0..124

    const int ty = tid >> 4;            // 0..15  -> rows ty*8..ty*8+7
    const int tx = tid & 15;            // 0..15  -> cols tx*8..tx*8+7

    float acc[8][8];
#pragma unroll
    for (int i = 0; i < 8; i++)
#pragma unroll
        for (int j = 0; j < 8; j++) acc[i][j] = 0.0f;

    const int aGRow = m0 + aRow;
    const bool aValid = (aGRow < M);

    for (int half = 0; half < 2; half++) {
        const float* A = half ? A2 : A1;
        const float* B = half ? B2 : B1;
        for (int k0 = 0; k0 < K; k0 += 8) {
            // load A tile (transposed into As[k][m])
            float4 av = make_float4(0.f, 0.f, 0.f, 0.f);
            if (aValid) av = *(const float4*)(A + (long)aGRow * K + k0 + aCol);
            As[aCol + 0][aRow] = av.x;
            As[aCol + 1][aRow] = av.y;
            As[aCol + 2][aRow] = av.z;
            As[aCol + 3][aRow] = av.w;
            // load B tile
            float4 bv = *(const float4*)(B + (long)(k0 + bRow) * N + n0 + bCol);
            *(float4*)&Bs[bRow][bCol] = bv;
            __syncthreads();

#pragma unroll
            for (int k = 0; k < 8; k++) {
                float a[8], b[8];
                float4 a0 = *(float4*)&As[k][ty * 8];
                float4 a1 = *(float4*)&As[k][ty * 8 + 4];
                a[0]=a0.x; a[1]=a0.y; a[2]=a0.z; a[3]=a0.w;
                a[4]=a1.x; a[5]=a1.y; a[6]=a1.z; a[7]=a1.w;
                float4 b0 = *(float4*)&Bs[k][tx * 8];
                float4 b1 = *(float4*)&Bs[k][tx * 8 + 4];
                b[0]=b0.x; b[1]=b0.y; b[2]=b0.z; b[3]=b0.w;
                b[4]=b1.x; b[5]=b1.y; b[6]=b1.z; b[7]=b1.w;
#pragma unroll
                for (int i = 0; i < 8; i++)
#pragma unroll
                    for (int j = 0; j < 8; j++)
                        acc[i][j] = fmaf(a[i], b[j], acc[i][j]);
            }
            __syncthreads();
        }
    }

    // epilogue
    float bvals[8];
#pragma unroll
    for (int j = 0; j < 8; j++) bvals[j] = bias[n0 + tx * 8 + j];

#pragma unroll
    for (int i = 0; i < 8; i++) {
        int row = m0 + ty * 8 + i;
        if (row >= M) continue;
        float out[8];
#pragma unroll
        for (int j = 0; j < 8; j++) {
            float v = acc[i][j] + bvals[j];
            if (RELU) v = fmaxf(v, 0.0f);
            out[j] = v;
        }
        float* cp = C + (long)row * N + n0 + tx * 8;
        *(float4*)(cp + 0) = make_float4(out[0], out[1], out[2], out[3]);
        *(float4*)(cp + 4) = make_float4(out[4], out[5], out[6], out[7]);
    }
}

// ---------------------------------------------------------------------------
extern "C" void kernel_launch(void* const* d_in, const int* in_sizes, int n_in,
                              void* d_out, int out_size) {
    const float* x       = (const float*)d_in[0];
    const float* W_self1 = (const float*)d_in[1];
    const float* W_neigh1= (const float*)d_in[2];
    const float* b1      = (const float*)d_in[3];
    const float* W_self2 = (const float*)d_in[4];
    const float* W_neigh2= (const float*)d_in[5];
    const float* b2      = (const float*)d_in[6];
    const int* e0_src    = (const int*)d_in[7];
    const int* e0_dst    = (const int*)d_in[8];
    const int* e1_src    = (const int*)d_in[9];
    const int* e1_dst    = (const int*)d_in[10];
    float* out = (float*)d_out;

    float *sum1, *deg0, *h1, *sum2, *deg1;
    cudaGetSymbolAddress((void**)&sum1, g_sum1);
    cudaGetSymbolAddress((void**)&deg0, g_deg0);
    cudaGetSymbolAddress((void**)&h1,   g_h1);
    cudaGetSymbolAddress((void**)&sum2, g_sum2);
    cudaGetSymbolAddress((void**)&deg1, g_deg1);

    // zero scratch
    zero_kernel<<<2048, 256>>>(sum1, (long)N_DST0 * IN_F);
    zero_kernel<<<80, 256>>>(deg0, N_DST0);
    zero_kernel<<<2048, 256>>>(sum2, (long)N_DST1 * H_F);
    zero_kernel<<<20, 256>>>(deg1, N_DST1);

    // ---- layer 1 aggregation ----
    deg_kernel<<<(E0 + 255) / 256, 256>>>(e0_dst, deg0, E0);
    {
        long total = (long)E0 * (IN_F / 4);
        scatter_kernel<<<(int)((total + 255) / 256), 256>>>(x, e0_src, e0_dst, sum1, E0, IN_F);
    }
    {
        long total = (long)N_DST0 * (IN_F / 4);
        normalize_kernel<<<(int)((total + 255) / 256), 256>>>(sum1, deg0, N_DST0, IN_F);
    }

    // ---- layer 1 GEMM: h1 = relu([x[:20000] | sum1] @ [Wself1; Wneigh1] + b1)
    {
        dim3 grid(H_F / 128, (N_DST0 + 127) / 128);
        sgemm_concat<true><<<grid, 256>>>(x, sum1, W_self1, W_neigh1, b1, h1,
                                          N_DST0, H_F, IN_F);
    }

    // ---- layer 2 aggregation ----
    deg_kernel<<<(E1 + 255) / 256, 256>>>(e1_dst, deg1, E1);
    {
        long total = (long)E1 * (H_F / 4);
        scatter_kernel<<<(int)((total + 255) / 256), 256>>>(h1, e1_src, e1_dst, sum2, E1, H_F);
    }
    {
        long total = (long)N_DST1 * (H_F / 4);
        normalize_kernel<<<(int)((total + 255) / 256), 256>>>(sum2, deg1, N_DST1, H_F);
    }

    // ---- layer 2 GEMM: out = [h1[:5000] | sum2] @ [Wself2; Wneigh2] + b2
    {
        dim3 grid(N_CLS / 128, (N_DST1 + 127) / 128);
        sgemm_concat<false><<<grid, 256>>>(h1, sum2, W_self2, W_neigh2, b2, out,
                                           N_DST1, N_CLS, H_F);
    }
    (void)in_sizes; (void)n_in; (void)out_size;
}

// round 4
// speedup vs baseline: 1.9610x; 1.9610x over previous
#include <cuda_runtime.h>
#include <cuda_bf16.h>
#include <cstdint>

// ---------------------------------------------------------------------------
// GraphSAGE 2-layer. Aggregation fp32 atomics; GEMMs via mma.sync bf16
// (m16n8k16, fp32 accum) with 2-way split: Ahi*Bhi + Alo*Bhi + Ahi*Blo.
//   N_SRC0=100000, N_DST0=20000, N_DST1=5000, E0=160000, E1=40000
//   IN_F=512, H_F=1024, N_CLS=256
// NOTE: build path targets base sm_103 PTX -> tcgen05 unavailable; HMMA path.
// ---------------------------------------------------------------------------

#define N_SRC0 100000
#define N_DST0 20000
#define N_DST1 5000
#define E0     160000
#define E1     40000
#define IN_F   512
#define H_F    1024
#define N_CLS  256

// ---------------- scratch (device globals; allocation forbidden) -----------
__device__ float g_sum1[(size_t)N_DST0 * IN_F];
__device__ float g_deg0[N_DST0];
__device__ float g_h1[(size_t)N_DST0 * H_F];
__device__ float g_sum2[(size_t)N_DST1 * H_F];
__device__ float g_deg1[N_DST1];
// transposed + split weights: bt[n*Ktot + k]
__device__ __nv_bfloat16 g_bt1_hi[(size_t)H_F * (2 * IN_F)];
__device__ __nv_bfloat16 g_bt1_lo[(size_t)H_F * (2 * IN_F)];
__device__ __nv_bfloat16 g_bt2_hi[(size_t)N_CLS * (2 * H_F)];
__device__ __nv_bfloat16 g_bt2_lo[(size_t)N_CLS * (2 * H_F)];

// ---------------- small kernels --------------------------------------------
__global__ void zero_kernel(float* p, long n) {
    long i = (long)blockIdx.x * blockDim.x + threadIdx.x;
    long st = (long)gridDim.x * blockDim.x;
    for (; i < n; i += st) p[i] = 0.0f;
}

__global__ void deg_kernel(const int* __restrict__ dst, float* __restrict__ deg, int E) {
    int e = blockIdx.x * blockDim.x + threadIdx.x;
    if (e < E) atomicAdd(&deg[dst[e]], 1.0f);
}

__global__ void scatter_kernel(const float* __restrict__ feat,
                               const int* __restrict__ src,
                               const int* __restrict__ dst,
                               float* __restrict__ out, int E, int F) {
    int per = F >> 2;
    long idx = (long)blockIdx.x * blockDim.x + threadIdx.x;
    if (idx >= (long)E * per) return;
    int e = (int)(idx / per);
    int c = (int)(idx % per) << 2;
    int s = src[e], d = dst[e];
    float4 v = *(const float4*)(feat + (long)s * F + c);
    float* o = out + (long)d * F + c;
    atomicAdd(o + 0, v.x);
    atomicAdd(o + 1, v.y);
    atomicAdd(o + 2, v.z);
    atomicAdd(o + 3, v.w);
}

__global__ void normalize_kernel(float* __restrict__ sum, const float* __restrict__ deg,
                                 int n, int F) {
    long idx = (long)blockIdx.x * blockDim.x + threadIdx.x;
    int per = F >> 2;
    if (idx >= (long)n * per) return;
    int row = (int)(idx / per);
    int c = (int)(idx % per) << 2;
    float inv = 1.0f / fmaxf(deg[row], 1.0f);
    float4* p = (float4*)(sum + (long)row * F + c);
    float4 v = *p;
    v.x *= inv; v.y *= inv; v.z *= inv; v.w *= inv;
    *p = v;
}

// Transpose+split weights:  bt[n*Ktot + k] = split(Wcat[k][n])
__global__ void transpose_split_kernel(const float* __restrict__ W0, const float* __restrict__ W1,
                                       int Khalf, int N, int Ktot,
                                       __nv_bfloat16* __restrict__ bhi,
                                       __nv_bfloat16* __restrict__ blo) {
    __shared__ float t[32][33];
    int k0 = blockIdx.x * 32, n0 = blockIdx.y * 32;
    int tx = threadIdx.x, ty = threadIdx.y;
#pragma unroll
    for (int j = 0; j < 32; j += 8) {
        int k = k0 + ty + j, n = n0 + tx;
        const float* W = (k < Khalf) ? (W0 + (size_t)k * N) : (W1 + (size_t)(k - Khalf) * N);
        t[ty + j][tx] = W[n];
    }
    __syncthreads();
#pragma unroll
    for (int j = 0; j < 32; j += 8) {
        int n = n0 + ty + j, k = k0 + tx;
        float f = t[tx][ty + j];
        __nv_bfloat16 h = __float2bfloat16_rn(f);
        float r = f - __bfloat162float(h);
        bhi[(size_t)n * Ktot + k] = h;
        blo[(size_t)n * Ktot + k] = __float2bfloat16_rn(r);
    }
}

// ---------------- warp-MMA primitives --------------------------------------
__device__ __forceinline__ uint32_t smem_u32(const void* p) {
    uint32_t a;
    asm("{ .reg .u64 t; cvta.to.shared.u64 t, %1; cvt.u32.u64 %0, t; }" : "=r"(a) : "l"(p));
    return a;
}
__device__ __forceinline__ void ldsm_x4(uint32_t r[4], uint32_t addr) {
    asm volatile("ldmatrix.sync.aligned.m8n8.x4.shared.b16 {%0,%1,%2,%3}, [%4];"
                 : "=r"(r[0]), "=r"(r[1]), "=r"(r[2]), "=r"(r[3]) : "r"(addr));
}
__device__ __forceinline__ void mma_bf16(float c[4], const uint32_t a[4], const uint32_t b0,
                                         const uint32_t b1) {
    asm volatile("mma.sync.aligned.m16n8k16.row.col.f32.bf16.bf16.f32 "
                 "{%0,%1,%2,%3}, {%4,%5,%6,%7}, {%8,%9}, {%0,%1,%2,%3};"
                 : "+f"(c[0]), "+f"(c[1]), "+f"(c[2]), "+f"(c[3])
                 : "r"(a[0]), "r"(a[1]), "r"(a[2]), "r"(a[3]), "r"(b0), "r"(b1));
}

// ---------------------------------------------------------------------------
// GEMM: C[M, ldC](cols n0..n0+BN) = [A1|A2](fp32) @ Bt^T + bias, optional ReLU.
// Bt: [Ntotal, Ktot] bf16 K-major, hi & lo. BK=32, 256 threads,
// warp grid 2(M) x 4(N), warp tile WM x WN. Padded smem rows (40 bf16 = 80B).
// ---------------------------------------------------------------------------
#define LDS_ROW 40   // bf16 elements per smem row (32 data + 8 pad)

template <int BM, int BN, int WM, int WN, bool RELU>
__global__ __launch_bounds__(256, 1)
void gemm_mma(const float* __restrict__ A1, const float* __restrict__ A2, int Khalf,
              const __nv_bfloat16* __restrict__ Bhi, const __nv_bfloat16* __restrict__ Blo,
              int Ktot, const float* __restrict__ bias, float* __restrict__ C,
              int M, int ldC) {
    extern __shared__ char smem[];
    // layout (bytes): Ah [BM][40], Al [BM][40], Bh [BN][40], Bl [BN][40]
    const int AH_OFF = 0;
    const int AL_OFF = BM * LDS_ROW * 2;
    const int BH_OFF = 2 * BM * LDS_ROW * 2;
    const int BL_OFF = 2 * BM * LDS_ROW * 2 + BN * LDS_ROW * 2;

    const uint32_t sb = smem_u32(smem);
    const int tid = threadIdx.x;
    const int wid = tid >> 5;
    const int lane = tid & 31;
    const int m0 = blockIdx.y * BM;
    const int n0 = blockIdx.x * BN;

    const int wm0 = (wid >> 2) * WM;
    const int wn0 = (wid & 3) * WN;

    constexpr int MT = WM / 16;   // m16 tiles per warp
    constexpr int NT = WN / 16;   // 16-wide n groups per warp (2 frags each)

    float acc[MT][WN / 8][4];
#pragma unroll
    for (int i = 0; i < MT; i++)
#pragma unroll
        for (int j = 0; j < WN / 8; j++)
#pragma unroll
            for (int q = 0; q < 4; q++) acc[i][j][q] = 0.0f;

    // ldmatrix source addresses (fixed per thread, advanced by ks)
    // A: lane l -> row (l%16), kcol (l/16)*8
    const uint32_t a_base = sb + ((wm0 + (lane & 15)) * LDS_ROW + (lane >> 4) * 8) * 2;
    // B: lane l -> row (l%8) + (l/16)*8, kcol ((l/8)%2)*8
    const uint32_t b_base = sb + ((wn0 + (lane & 7) + ((lane >> 4) << 3)) * LDS_ROW +
                                  (((lane >> 3) & 1) << 3)) * 2;

    const int nChunks = Ktot / 32;
    for (int c = 0; c < nChunks; c++) {
        const int kg = c * 32;
        const float* A = (kg < Khalf) ? A1 : A2;
        const int ka = (kg < Khalf) ? kg : (kg - Khalf);

        // ---- stage A: BM x 32 fp32 -> hi/lo bf16 ----
        {
            constexpr int ITER = BM / 32;          // float4 loads per thread
#pragma unroll
            for (int i = 0; i < ITER; i++) {
                int f = tid + i * 256;
                int row = f >> 3;
                int k4 = (f & 7) << 2;
                float4 v = make_float4(0.f, 0.f, 0.f, 0.f);
                if (m0 + row < M)
                    v = *(const float4*)(A + (size_t)(m0 + row) * Khalf + ka + k4);
                __nv_bfloat16 h0 = __float2bfloat16_rn(v.x);
                __nv_bfloat16 h1 = __float2bfloat16_rn(v.y);
                __nv_bfloat16 h2 = __float2bfloat16_rn(v.z);
                __nv_bfloat16 h3 = __float2bfloat16_rn(v.w);
                __nv_bfloat162 hp0 = __nv_bfloat162(h0, h1);
                __nv_bfloat162 hp1 = __nv_bfloat162(h2, h3);
                __nv_bfloat162 lp0 = __nv_bfloat162(__float2bfloat16_rn(v.x - __bfloat162float(h0)),
                                                    __float2bfloat16_rn(v.y - __bfloat162float(h1)));
                __nv_bfloat162 lp1 = __nv_bfloat162(__float2bfloat16_rn(v.z - __bfloat162float(h2)),
                                                    __float2bfloat16_rn(v.w - __bfloat162float(h3)));
                int off = (row * LDS_ROW + k4) * 2;
                *(uint2*)(smem + AH_OFF + off) = make_uint2(*(uint32_t*)&hp0, *(uint32_t*)&hp1);
                *(uint2*)(smem + AL_OFF + off) = make_uint2(*(uint32_t*)&lp0, *(uint32_t*)&lp1);
            }
        }
        // ---- stage B: BN x 32 bf16 hi + lo ----
        {
            constexpr int ITER = BN / 64;          // uint4 per thread per matrix
#pragma unroll
            for (int i = 0; i < ITER; i++) {
                int g = tid + i * 256;
                int row = g >> 2;
                int k8 = (g & 3) << 3;
                size_t goff = (size_t)(n0 + row) * Ktot + kg + k8;
                int off = (row * LDS_ROW + k8) * 2;
                *(uint4*)(smem + BH_OFF + off) = *(const uint4*)(Bhi + goff);
                *(uint4*)(smem + BL_OFF + off) = *(const uint4*)(Blo + goff);
            }
        }
        __syncthreads();

        // ---- compute: 2 k16-steps x 3 split terms ----
#pragma unroll
        for (int ks = 0; ks < 2; ks++) {
            const uint32_t akoff = ks * 32;  // 16 bf16 = 32 bytes
            uint32_t ah[MT][4], al[MT][4], bh[NT][4];
#pragma unroll
            for (int mi = 0; mi < MT; mi++)
                ldsm_x4(ah[mi], a_base + AH_OFF + mi * (16 * LDS_ROW * 2) + akoff);
#pragma unroll
            for (int nj = 0; nj < NT; nj++)
                ldsm_x4(bh[nj], b_base + BH_OFF + nj * (16 * LDS_ROW * 2) + akoff);
            // hh
#pragma unroll
            for (int mi = 0; mi < MT; mi++)
#pragma unroll
                for (int nj = 0; nj < NT; nj++) {
                    mma_bf16(acc[mi][2 * nj + 0], ah[mi], bh[nj][0], bh[nj][1]);
                    mma_bf16(acc[mi][2 * nj + 1], ah[mi], bh[nj][2], bh[nj][3]);
                }
            // lh
#pragma unroll
            for (int mi = 0; mi < MT; mi++)
                ldsm_x4(al[mi], a_base + AL_OFF + mi * (16 * LDS_ROW * 2) + akoff);
#pragma unroll
            for (int mi = 0; mi < MT; mi++)
#pragma unroll
                for (int nj = 0; nj < NT; nj++) {
                    mma_bf16(acc[mi][2 * nj + 0], al[mi], bh[nj][0], bh[nj][1]);
                    mma_bf16(acc[mi][2 * nj + 1], al[mi], bh[nj][2], bh[nj][3]);
                }
            // hl
#pragma unroll
            for (int nj = 0; nj < NT; nj++) {
                uint32_t bl[4];
                ldsm_x4(bl, b_base + BL_OFF + nj * (16 * LDS_ROW * 2) + akoff);
#pragma unroll
                for (int mi = 0; mi < MT; mi++) {
                    mma_bf16(acc[mi][2 * nj + 0], ah[mi], bl[0], bl[1]);
                    mma_bf16(acc[mi][2 * nj + 1], ah[mi], bl[2], bl[3]);
                }
            }
        }
        __syncthreads();
    }

    // ---- epilogue ----
#pragma unroll
    for (int mi = 0; mi < MT; mi++) {
#pragma unroll
        for (int nf = 0; nf < WN / 8; nf++) {
            int col = n0 + wn0 + nf * 8 + (lane & 3) * 2;
            float bx = bias[col], by = bias[col + 1];
            int r0 = m0 + wm0 + mi * 16 + (lane >> 2);
            float* c = acc[mi][nf];
            if (r0 < M) {
                float ox = c[0] + bx, oy = c[1] + by;
                if (RELU) { ox = fmaxf(ox, 0.f); oy = fmaxf(oy, 0.f); }
                *(float2*)(C + (size_t)r0 * ldC + col) = make_float2(ox, oy);
            }
            int r1 = r0 + 8;
            if (r1 < M) {
                float ox = c[2] + bx, oy = c[3] + by;
                if (RELU) { ox = fmaxf(ox, 0.f); oy = fmaxf(oy, 0.f); }
                *(float2*)(C + (size_t)r1 * ldC + col) = make_float2(ox, oy);
            }
        }
    }
}

// smem bytes for a tile config
#define GSMEM(BM, BN) ((2 * (BM) + 2 * (BN)) * LDS_ROW * 2)

// ---------------------------------------------------------------------------
extern "C" void kernel_launch(void* const* d_in, const int* in_sizes, int n_in,
                              void* d_out, int out_size) {
    const float* x        = (const float*)d_in[0];
    const float* W_self1  = (const float*)d_in[1];
    const float* W_neigh1 = (const float*)d_in[2];
    const float* b1       = (const float*)d_in[3];
    const float* W_self2  = (const float*)d_in[4];
    const float* W_neigh2 = (const float*)d_in[5];
    const float* b2       = (const float*)d_in[6];
    const int* e0_src     = (const int*)d_in[7];
    const int* e0_dst     = (const int*)d_in[8];
    const int* e1_src     = (const int*)d_in[9];
    const int* e1_dst     = (const int*)d_in[10];
    float* out = (float*)d_out;

    float *sum1, *deg0, *h1, *sum2, *deg1;
    __nv_bfloat16 *bt1h, *bt1l, *bt2h, *bt2l;
    cudaGetSymbolAddress((void**)&sum1, g_sum1);
    cudaGetSymbolAddress((void**)&deg0, g_deg0);
    cudaGetSymbolAddress((void**)&h1,   g_h1);
    cudaGetSymbolAddress((void**)&sum2, g_sum2);
    cudaGetSymbolAddress((void**)&deg1, g_deg1);
    cudaGetSymbolAddress((void**)&bt1h, g_bt1_hi);
    cudaGetSymbolAddress((void**)&bt1l, g_bt1_lo);
    cudaGetSymbolAddress((void**)&bt2h, g_bt2_hi);
    cudaGetSymbolAddress((void**)&bt2l, g_bt2_lo);

    cudaFuncSetAttribute((const void*)gemm_mma<128, 256, 64, 64, true>,
                         cudaFuncAttributeMaxDynamicSharedMemorySize, GSMEM(128, 256));
    cudaFuncSetAttribute((const void*)gemm_mma<64, 128, 32, 32, false>,
                         cudaFuncAttributeMaxDynamicSharedMemorySize, GSMEM(64, 128));

    // weight transpose + split
    {
        dim3 blk(32, 8);
        dim3 g1(2 * IN_F / 32, H_F / 32);
        transpose_split_kernel<<<g1, blk>>>(W_self1, W_neigh1, IN_F, H_F, 2 * IN_F, bt1h, bt1l);
        dim3 g2(2 * H_F / 32, N_CLS / 32);
        transpose_split_kernel<<<g2, blk>>>(W_self2, W_neigh2, H_F, N_CLS, 2 * H_F, bt2h, bt2l);
    }

    // zero scratch
    zero_kernel<<<2048, 256>>>(sum1, (long)N_DST0 * IN_F);
    zero_kernel<<<80, 256>>>(deg0, N_DST0);
    zero_kernel<<<2048, 256>>>(sum2, (long)N_DST1 * H_F);
    zero_kernel<<<20, 256>>>(deg1, N_DST1);

    // ---- layer 1 aggregation ----
    deg_kernel<<<(E0 + 255) / 256, 256>>>(e0_dst, deg0, E0);
    {
        long total = (long)E0 * (IN_F / 4);
        scatter_kernel<<<(int)((total + 255) / 256), 256>>>(x, e0_src, e0_dst, sum1, E0, IN_F);
    }
    {
        long total = (long)N_DST0 * (IN_F / 4);
        normalize_kernel<<<(int)((total + 255) / 256), 256>>>(sum1, deg0, N_DST0, IN_F);
    }

    // ---- layer 1 GEMM: h1 = relu([x|sum1] @ Bt1^T + b1) ----
    {
        dim3 grid(H_F / 256, (N_DST0 + 127) / 128);  // (4, 157)
        gemm_mma<128, 256, 64, 64, true><<<grid, 256, GSMEM(128, 256)>>>(
            x, sum1, IN_F, bt1h, bt1l, 2 * IN_F, b1, h1, N_DST0, H_F);
    }

    // ---- layer 2 aggregation ----
    deg_kernel<<<(E1 + 255) / 256, 256>>>(e1_dst, deg1, E1);
    {
        long total = (long)E1 * (H_F / 4);
        scatter_kernel<<<(int)((total + 255) / 256), 256>>>(h1, e1_src, e1_dst, sum2, E1, H_F);
    }
    {
        long total = (long)N_DST1 * (H_F / 4);
        normalize_kernel<<<(int)((total + 255) / 256), 256>>>(sum2, deg1, N_DST1, H_F);
    }

    // ---- layer 2 GEMM: out = [h1|sum2] @ Bt2^T + b2 ----
    {
        dim3 grid(N_CLS / 128, (N_DST1 + 63) / 64);  // (2, 79)
        gemm_mma<64, 128, 32, 32, false><<<grid, 256, GSMEM(64, 128)>>>(
            h1, sum2, H_F, bt2h, bt2l, 2 * H_F, b2, out, N_DST1, N_CLS);
    }
    (void)in_sizes; (void)n_in; (void)out_size;
}

// round 5
// speedup vs baseline: 2.4786x; 1.2640x over previous
#include <cuda_runtime.h>
#include <cuda_bf16.h>
#include <cstdint>

// ---------------------------------------------------------------------------
// GraphSAGE 2-layer. Aggregation via CSR gather (no feature atomics);
// GEMMs via mma.sync bf16 (m16n8k16, fp32 accum) with 2-way split:
// Ahi*Bhi + Alo*Bhi + Ahi*Blo.
//   N_SRC0=100000, N_DST0=20000, N_DST1=5000, E0=160000, E1=40000
//   IN_F=512, H_F=1024, N_CLS=256
// ---------------------------------------------------------------------------

#define N_SRC0 100000
#define N_DST0 20000
#define N_DST1 5000
#define E0     160000
#define E1     40000
#define IN_F   512
#define H_F    1024
#define N_CLS  256

// ---------------- scratch (device globals; allocation forbidden) -----------
__device__ float g_sum1[(size_t)N_DST0 * IN_F];
__device__ float g_h1[(size_t)N_DST0 * H_F];
__device__ float g_sum2[(size_t)N_DST1 * H_F];
// CSR scratch
__device__ int g_cnt0[N_DST0];
__device__ int g_rowptr0[N_DST0 + 1];
__device__ int g_cursor0[N_DST0];
__device__ int g_perm0[E0];
__device__ int g_cnt1[N_DST1];
__device__ int g_rowptr1[N_DST1 + 1];
__device__ int g_cursor1[N_DST1];
__device__ int g_perm1[E1];
// transposed + split weights: bt[n*Ktot + k]
__device__ __nv_bfloat16 g_bt1_hi[(size_t)H_F * (2 * IN_F)];
__device__ __nv_bfloat16 g_bt1_lo[(size_t)H_F * (2 * IN_F)];
__device__ __nv_bfloat16 g_bt2_hi[(size_t)N_CLS * (2 * H_F)];
__device__ __nv_bfloat16 g_bt2_lo[(size_t)N_CLS * (2 * H_F)];

// ---------------- CSR build kernels ----------------------------------------
__global__ void zero_int_kernel(int* p, int n) {
    int i = blockIdx.x * blockDim.x + threadIdx.x;
    if (i < n) p[i] = 0;
}

__global__ void count_kernel(const int* __restrict__ dst, int* __restrict__ cnt, int E) {
    int e = blockIdx.x * blockDim.x + threadIdx.x;
    if (e < E) atomicAdd(&cnt[dst[e]], 1);
}

// single-block chunked exclusive scan: rowptr[0..n] and cursor copy
__global__ void scan_kernel(const int* __restrict__ cnt, int* __restrict__ rowptr,
                            int* __restrict__ cursor, int n) {
    __shared__ int s[1024];
    __shared__ int carry_s;
    int tid = threadIdx.x;
    if (tid == 0) carry_s = 0;
    __syncthreads();
    for (int base = 0; base < n; base += 1024) {
        int i = base + tid;
        int v = (i < n) ? cnt[i] : 0;
        s[tid] = v;
        __syncthreads();
#pragma unroll
        for (int off = 1; off < 1024; off <<= 1) {
            int t = (tid >= off) ? s[tid - off] : 0;
            __syncthreads();
            s[tid] += t;
            __syncthreads();
        }
        int carry = carry_s;
        int excl = s[tid] - v + carry;
        if (i < n) { rowptr[i] = excl; cursor[i] = excl; }
        int total = s[1023];
        __syncthreads();
        if (tid == 0) carry_s = carry + total;
        __syncthreads();
    }
    if (tid == 0) rowptr[n] = carry_s;
}

__global__ void fill_kernel(const int* __restrict__ src, const int* __restrict__ dst,
                            int* __restrict__ cursor, int* __restrict__ perm, int E) {
    int e = blockIdx.x * blockDim.x + threadIdx.x;
    if (e < E) {
        int pos = atomicAdd(&cursor[dst[e]], 1);
        perm[pos] = src[e];
    }
}

// ---------------- gather aggregation (warp per dst row, fused normalize) ----
template <int F>
__global__ void aggregate_kernel(const float* __restrict__ feat,
                                 const int* __restrict__ rowptr,
                                 const int* __restrict__ perm,
                                 float* __restrict__ out, int n) {
    int w = (blockIdx.x * blockDim.x + threadIdx.x) >> 5;
    if (w >= n) return;
    int lane = threadIdx.x & 31;
    int beg = rowptr[w], end = rowptr[w + 1];
    constexpr int V = F / 128;  // float4 per lane
    float4 acc[V];
#pragma unroll
    for (int v = 0; v < V; v++) acc[v] = make_float4(0.f, 0.f, 0.f, 0.f);
    for (int e = beg; e < end; e++) {
        const float4* p = (const float4*)(feat + (size_t)perm[e] * F) + lane;
#pragma unroll
        for (int v = 0; v < V; v++) {
            float4 t = p[v * 32];
            acc[v].x += t.x; acc[v].y += t.y; acc[v].z += t.z; acc[v].w += t.w;
        }
    }
    float inv = 1.0f / (float)max(end - beg, 1);
    float4* o = (float4*)(out + (size_t)w * F) + lane;
#pragma unroll
    for (int v = 0; v < V; v++) {
        acc[v].x *= inv; acc[v].y *= inv; acc[v].z *= inv; acc[v].w *= inv;
        o[v * 32] = acc[v];
    }
}

// ---------------- weight transpose + split ----------------------------------
__global__ void transpose_split_kernel(const float* __restrict__ W0, const float* __restrict__ W1,
                                       int Khalf, int N, int Ktot,
                                       __nv_bfloat16* __restrict__ bhi,
                                       __nv_bfloat16* __restrict__ blo) {
    __shared__ float t[32][33];
    int k0 = blockIdx.x * 32, n0 = blockIdx.y * 32;
    int tx = threadIdx.x, ty = threadIdx.y;
#pragma unroll
    for (int j = 0; j < 32; j += 8) {
        int k = k0 + ty + j, n = n0 + tx;
        const float* W = (k < Khalf) ? (W0 + (size_t)k * N) : (W1 + (size_t)(k - Khalf) * N);
        t[ty + j][tx] = W[n];
    }
    __syncthreads();
#pragma unroll
    for (int j = 0; j < 32; j += 8) {
        int n = n0 + ty + j, k = k0 + tx;
        float f = t[tx][ty + j];
        __nv_bfloat16 h = __float2bfloat16_rn(f);
        float r = f - __bfloat162float(h);
        bhi[(size_t)n * Ktot + k] = h;
        blo[(size_t)n * Ktot + k] = __float2bfloat16_rn(r);
    }
}

// ---------------- warp-MMA primitives --------------------------------------
__device__ __forceinline__ uint32_t smem_u32(const void* p) {
    uint32_t a;
    asm("{ .reg .u64 t; cvta.to.shared.u64 t, %1; cvt.u32.u64 %0, t; }" : "=r"(a) : "l"(p));
    return a;
}
__device__ __forceinline__ void ldsm_x4(uint32_t r[4], uint32_t addr) {
    asm volatile("ldmatrix.sync.aligned.m8n8.x4.shared.b16 {%0,%1,%2,%3}, [%4];"
                 : "=r"(r[0]), "=r"(r[1]), "=r"(r[2]), "=r"(r[3]) : "r"(addr));
}
__device__ __forceinline__ void mma_bf16(float c[4], const uint32_t a[4], const uint32_t b0,
                                         const uint32_t b1) {
    asm volatile("mma.sync.aligned.m16n8k16.row.col.f32.bf16.bf16.f32 "
                 "{%0,%1,%2,%3}, {%4,%5,%6,%7}, {%8,%9}, {%0,%1,%2,%3};"
                 : "+f"(c[0]), "+f"(c[1]), "+f"(c[2]), "+f"(c[3])
                 : "r"(a[0]), "r"(a[1]), "r"(a[2]), "r"(a[3]), "r"(b0), "r"(b1));
}

// ---------------------------------------------------------------------------
// GEMM: C[M, ldC](cols n0..n0+BN) = [A1|A2](fp32) @ Bt^T + bias, optional ReLU.
// Bt: [Ntotal, Ktot] bf16 K-major, hi & lo. BK=32, 256 threads,
// warp grid 2(M) x 4(N), warp tile WM x WN. Padded smem rows (40 bf16 = 80B).
// ---------------------------------------------------------------------------
#define LDS_ROW 40

template <int BM, int BN, int WM, int WN, bool RELU>
__global__ __launch_bounds__(256, 1)
void gemm_mma(const float* __restrict__ A1, const float* __restrict__ A2, int Khalf,
              const __nv_bfloat16* __restrict__ Bhi, const __nv_bfloat16* __restrict__ Blo,
              int Ktot, const float* __restrict__ bias, float* __restrict__ C,
              int M, int ldC) {
    extern __shared__ char smem[];
    const int AH_OFF = 0;
    const int AL_OFF = BM * LDS_ROW * 2;
    const int BH_OFF = 2 * BM * LDS_ROW * 2;
    const int BL_OFF = 2 * BM * LDS_ROW * 2 + BN * LDS_ROW * 2;

    const uint32_t sb = smem_u32(smem);
    const int tid = threadIdx.x;
    const int wid = tid >> 5;
    const int lane = tid & 31;
    const int m0 = blockIdx.y * BM;
    const int n0 = blockIdx.x * BN;

    const int wm0 = (wid >> 2) * WM;
    const int wn0 = (wid & 3) * WN;

    constexpr int MT = WM / 16;
    constexpr int NT = WN / 16;

    float acc[MT][WN / 8][4];
#pragma unroll
    for (int i = 0; i < MT; i++)
#pragma unroll
        for (int j = 0; j < WN / 8; j++)
#pragma unroll
            for (int q = 0; q < 4; q++) acc[i][j][q] = 0.0f;

    const uint32_t a_base = sb + ((wm0 + (lane & 15)) * LDS_ROW + (lane >> 4) * 8) * 2;
    const uint32_t b_base = sb + ((wn0 + (lane & 7) + ((lane >> 4) << 3)) * LDS_ROW +
                                  (((lane >> 3) & 1) << 3)) * 2;

    const int nChunks = Ktot / 32;
    for (int c = 0; c < nChunks; c++) {
        const int kg = c * 32;
        const float* A = (kg < Khalf) ? A1 : A2;
        const int ka = (kg < Khalf) ? kg : (kg - Khalf);

        {
            constexpr int ITER = BM / 32;
#pragma unroll
            for (int i = 0; i < ITER; i++) {
                int f = tid + i * 256;
                int row = f >> 3;
                int k4 = (f & 7) << 2;
                float4 v = make_float4(0.f, 0.f, 0.f, 0.f);
                if (m0 + row < M)
                    v = *(const float4*)(A + (size_t)(m0 + row) * Khalf + ka + k4);
                __nv_bfloat16 h0 = __float2bfloat16_rn(v.x);
                __nv_bfloat16 h1 = __float2bfloat16_rn(v.y);
                __nv_bfloat16 h2 = __float2bfloat16_rn(v.z);
                __nv_bfloat16 h3 = __float2bfloat16_rn(v.w);
                __nv_bfloat162 hp0 = __nv_bfloat162(h0, h1);
                __nv_bfloat162 hp1 = __nv_bfloat162(h2, h3);
                __nv_bfloat162 lp0 = __nv_bfloat162(__float2bfloat16_rn(v.x - __bfloat162float(h0)),
                                                    __float2bfloat16_rn(v.y - __bfloat162float(h1)));
                __nv_bfloat162 lp1 = __nv_bfloat162(__float2bfloat16_rn(v.z - __bfloat162float(h2)),
                                                    __float2bfloat16_rn(v.w - __bfloat162float(h3)));
                int off = (row * LDS_ROW + k4) * 2;
                *(uint2*)(smem + AH_OFF + off) = make_uint2(*(uint32_t*)&hp0, *(uint32_t*)&hp1);
                *(uint2*)(smem + AL_OFF + off) = make_uint2(*(uint32_t*)&lp0, *(uint32_t*)&lp1);
            }
        }
        {
            constexpr int ITER = BN / 64;
#pragma unroll
            for (int i = 0; i < ITER; i++) {
                int g = tid + i * 256;
                int row = g >> 2;
                int k8 = (g & 3) << 3;
                size_t goff = (size_t)(n0 + row) * Ktot + kg + k8;
                int off = (row * LDS_ROW + k8) * 2;
                *(uint4*)(smem + BH_OFF + off) = *(const uint4*)(Bhi + goff);
                *(uint4*)(smem + BL_OFF + off) = *(const uint4*)(Blo + goff);
            }
        }
        __syncthreads();

#pragma unroll
        for (int ks = 0; ks < 2; ks++) {
            const uint32_t akoff = ks * 32;
            uint32_t ah[MT][4], al[MT][4], bh[NT][4];
#pragma unroll
            for (int mi = 0; mi < MT; mi++)
                ldsm_x4(ah[mi], a_base + AH_OFF + mi * (16 * LDS_ROW * 2) + akoff);
#pragma unroll
            for (int nj = 0; nj < NT; nj++)
                ldsm_x4(bh[nj], b_base + BH_OFF + nj * (16 * LDS_ROW * 2) + akoff);
#pragma unroll
            for (int mi = 0; mi < MT; mi++)
#pragma unroll
                for (int nj = 0; nj < NT; nj++) {
                    mma_bf16(acc[mi][2 * nj + 0], ah[mi], bh[nj][0], bh[nj][1]);
                    mma_bf16(acc[mi][2 * nj + 1], ah[mi], bh[nj][2], bh[nj][3]);
                }
#pragma unroll
            for (int mi = 0; mi < MT; mi++)
                ldsm_x4(al[mi], a_base + AL_OFF + mi * (16 * LDS_ROW * 2) + akoff);
#pragma unroll
            for (int mi = 0; mi < MT; mi++)
#pragma unroll
                for (int nj = 0; nj < NT; nj++) {
                    mma_bf16(acc[mi][2 * nj + 0], al[mi], bh[nj][0], bh[nj][1]);
                    mma_bf16(acc[mi][2 * nj + 1], al[mi], bh[nj][2], bh[nj][3]);
                }
#pragma unroll
            for (int nj = 0; nj < NT; nj++) {
                uint32_t bl[4];
                ldsm_x4(bl, b_base + BL_OFF + nj * (16 * LDS_ROW * 2) + akoff);
#pragma unroll
                for (int mi = 0; mi < MT; mi++) {
                    mma_bf16(acc[mi][2 * nj + 0], ah[mi], bl[0], bl[1]);
                    mma_bf16(acc[mi][2 * nj + 1], ah[mi], bl[2], bl[3]);
                }
            }
        }
        __syncthreads();
    }

#pragma unroll
    for (int mi = 0; mi < MT; mi++) {
#pragma unroll
        for (int nf = 0; nf < WN / 8; nf++) {
            int col = n0 + wn0 + nf * 8 + (lane & 3) * 2;
            float bx = bias[col], by = bias[col + 1];
            int r0 = m0 + wm0 + mi * 16 + (lane >> 2);
            float* c = acc[mi][nf];
            if (r0 < M) {
                float ox = c[0] + bx, oy = c[1] + by;
                if (RELU) { ox = fmaxf(ox, 0.f); oy = fmaxf(oy, 0.f); }
                *(float2*)(C + (size_t)r0 * ldC + col) = make_float2(ox, oy);
            }
            int r1 = r0 + 8;
            if (r1 < M) {
                float ox = c[2] + bx, oy = c[3] + by;
                if (RELU) { ox = fmaxf(ox, 0.f); oy = fmaxf(oy, 0.f); }
                *(float2*)(C + (size_t)r1 * ldC + col) = make_float2(ox, oy);
            }
        }
    }
}

#define GSMEM(BM, BN) ((2 * (BM) + 2 * (BN)) * LDS_ROW * 2)

// ---------------------------------------------------------------------------
extern "C" void kernel_launch(void* const* d_in, const int* in_sizes, int n_in,
                              void* d_out, int out_size) {
    const float* x        = (const float*)d_in[0];
    const float* W_self1  = (const float*)d_in[1];
    const float* W_neigh1 = (const float*)d_in[2];
    const float* b1       = (const float*)d_in[3];
    const float* W_self2  = (const float*)d_in[4];
    const float* W_neigh2 = (const float*)d_in[5];
    const float* b2       = (const float*)d_in[6];
    const int* e0_src     = (const int*)d_in[7];
    const int* e0_dst     = (const int*)d_in[8];
    const int* e1_src     = (const int*)d_in[9];
    const int* e1_dst     = (const int*)d_in[10];
    float* out = (float*)d_out;

    float *sum1, *h1, *sum2;
    int *cnt0, *rowptr0, *cursor0, *perm0, *cnt1, *rowptr1, *cursor1, *perm1;
    __nv_bfloat16 *bt1h, *bt1l, *bt2h, *bt2l;
    cudaGetSymbolAddress((void**)&sum1, g_sum1);
    cudaGetSymbolAddress((void**)&h1,   g_h1);
    cudaGetSymbolAddress((void**)&sum2, g_sum2);
    cudaGetSymbolAddress((void**)&cnt0, g_cnt0);
    cudaGetSymbolAddress((void**)&rowptr0, g_rowptr0);
    cudaGetSymbolAddress((void**)&cursor0, g_cursor0);
    cudaGetSymbolAddress((void**)&perm0, g_perm0);
    cudaGetSymbolAddress((void**)&cnt1, g_cnt1);
    cudaGetSymbolAddress((void**)&rowptr1, g_rowptr1);
    cudaGetSymbolAddress((void**)&cursor1, g_cursor1);
    cudaGetSymbolAddress((void**)&perm1, g_perm1);
    cudaGetSymbolAddress((void**)&bt1h, g_bt1_hi);
    cudaGetSymbolAddress((void**)&bt1l, g_bt1_lo);
    cudaGetSymbolAddress((void**)&bt2h, g_bt2_hi);
    cudaGetSymbolAddress((void**)&bt2l, g_bt2_lo);

    cudaFuncSetAttribute((const void*)gemm_mma<128, 256, 64, 64, true>,
                         cudaFuncAttributeMaxDynamicSharedMemorySize, GSMEM(128, 256));
    cudaFuncSetAttribute((const void*)gemm_mma<64, 128, 32, 32, false>,
                         cudaFuncAttributeMaxDynamicSharedMemorySize, GSMEM(64, 128));

    // ---- layer 1: CSR build (launch indices 0-3) ----
    zero_int_kernel<<<(N_DST0 + 255) / 256, 256>>>(cnt0, N_DST0);
    count_kernel<<<(E0 + 255) / 256, 256>>>(e0_dst, cnt0, E0);
    scan_kernel<<<1, 1024>>>(cnt0, rowptr0, cursor0, N_DST0);
    fill_kernel<<<(E0 + 255) / 256, 256>>>(e0_src, e0_dst, cursor0, perm0, E0);

    // weight transpose+split for layer 1 (index 4)
    {
        dim3 blk(32, 8);
        dim3 g1(2 * IN_F / 32, H_F / 32);
        transpose_split_kernel<<<g1, blk>>>(W_self1, W_neigh1, IN_F, H_F, 2 * IN_F, bt1h, bt1l);
    }

    // gather aggregation (index 5 — ncu-profiled launch)
    aggregate_kernel<IN_F><<<(N_DST0 * 32 + 255) / 256, 256>>>(x, rowptr0, perm0, sum1, N_DST0);

    // ---- layer 1 GEMM: h1 = relu([x|sum1] @ Bt1^T + b1) ----
    {
        dim3 grid(H_F / 256, (N_DST0 + 127) / 128);
        gemm_mma<128, 256, 64, 64, true><<<grid, 256, GSMEM(128, 256)>>>(
            x, sum1, IN_F, bt1h, bt1l, 2 * IN_F, b1, h1, N_DST0, H_F);
    }

    // weight transpose+split for layer 2
    {
        dim3 blk(32, 8);
        dim3 g2(2 * H_F / 32, N_CLS / 32);
        transpose_split_kernel<<<g2, blk>>>(W_self2, W_neigh2, H_F, N_CLS, 2 * H_F, bt2h, bt2l);
    }

    // ---- layer 2: CSR build + aggregate ----
    zero_int_kernel<<<(N_DST1 + 255) / 256, 256>>>(cnt1, N_DST1);
    count_kernel<<<(E1 + 255) / 256, 256>>>(e1_dst, cnt1, E1);
    scan_kernel<<<1, 1024>>>(cnt1, rowptr1, cursor1, N_DST1);
    fill_kernel<<<(E1 + 255) / 256, 256>>>(e1_src, e1_dst, cursor1, perm1, E1);
    aggregate_kernel<H_F><<<(N_DST1 * 32 + 255) / 256, 256>>>(h1, rowptr1, perm1, sum2, N_DST1);

    // ---- layer 2 GEMM: out = [h1|sum2] @ Bt2^T + b2 ----
    {
        dim3 grid(N_CLS / 128, (N_DST1 + 63) / 64);
        gemm_mma<64, 128, 32, 32, false><<<grid, 256, GSMEM(64, 128)>>>(
            h1, sum2, H_F, bt2h, bt2l, 2 * H_F, b2, out, N_DST1, N_CLS);
    }
    (void)in_sizes; (void)n_in; (void)out_size;
}

// round 6
// speedup vs baseline: 2.8823x; 1.1629x over previous
#include <cuda_runtime.h>
#include <cuda_bf16.h>
#include <cstdint>

// ---------------------------------------------------------------------------
// GraphSAGE 2-layer. CSR gather aggregation (emits bf16 hi/lo);
// GEMMs: mma.sync bf16 m16n8k16, 2-way split (Ahi*Bhi + Alo*Bhi + Ahi*Blo),
// cp.async double-buffered stages, pure-bf16 operands.
//   N_SRC0=100000, N_DST0=20000, N_DST1=5000, E0=160000, E1=40000
//   IN_F=512, H_F=1024, N_CLS=256
// ---------------------------------------------------------------------------

#define N_SRC0 100000
#define N_DST0 20000
#define N_DST1 5000
#define E0     160000
#define E1     40000
#define IN_F   512
#define H_F    1024
#define N_CLS  256

// ---------------- scratch (device globals; allocation forbidden) -----------
__device__ float g_h1[(size_t)N_DST0 * H_F];
// bf16 split operand buffers
__device__ __nv_bfloat16 g_xs_hi[(size_t)N_DST0 * IN_F];
__device__ __nv_bfloat16 g_xs_lo[(size_t)N_DST0 * IN_F];
__device__ __nv_bfloat16 g_s1_hi[(size_t)N_DST0 * IN_F];
__device__ __nv_bfloat16 g_s1_lo[(size_t)N_DST0 * IN_F];
__device__ __nv_bfloat16 g_h1s_hi[(size_t)N_DST1 * H_F];
__device__ __nv_bfloat16 g_h1s_lo[(size_t)N_DST1 * H_F];
__device__ __nv_bfloat16 g_s2_hi[(size_t)N_DST1 * H_F];
__device__ __nv_bfloat16 g_s2_lo[(size_t)N_DST1 * H_F];
// CSR scratch
__device__ int g_cnt0[N_DST0];
__device__ int g_rowptr0[N_DST0 + 1];
__device__ int g_cursor0[N_DST0];
__device__ int g_perm0[E0];
__device__ int g_cnt1[N_DST1];
__device__ int g_rowptr1[N_DST1 + 1];
__device__ int g_cursor1[N_DST1];
__device__ int g_perm1[E1];
// transposed + split weights: bt[n*Ktot + k]
__device__ __nv_bfloat16 g_bt1_hi[(size_t)H_F * (2 * IN_F)];
__device__ __nv_bfloat16 g_bt1_lo[(size_t)H_F * (2 * IN_F)];
__device__ __nv_bfloat16 g_bt2_hi[(size_t)N_CLS * (2 * H_F)];
__device__ __nv_bfloat16 g_bt2_lo[(size_t)N_CLS * (2 * H_F)];

// ---------------- helpers ---------------------------------------------------
__device__ __forceinline__ uint32_t smem_u32(const void* p) {
    uint32_t a;
    asm("{ .reg .u64 t; cvta.to.shared.u64 t, %1; cvt.u32.u64 %0, t; }" : "=r"(a) : "l"(p));
    return a;
}
__device__ __forceinline__ void cp16(uint32_t dst, const void* src, bool pred) {
    int sz = pred ? 16 : 0;
    asm volatile("cp.async.cg.shared.global [%0], [%1], 16, %2;"
                 :: "r"(dst), "l"(src), "r"(sz));
}
#define CP_COMMIT() asm volatile("cp.async.commit_group;" ::: "memory")

__device__ __forceinline__ uint32_t pack_hi(float a, float b) {
    __nv_bfloat162 h = __nv_bfloat162(__float2bfloat16_rn(a), __float2bfloat16_rn(b));
    return *(uint32_t*)&h;
}
__device__ __forceinline__ uint32_t pack_lo(float a, float b) {
    float ra = a - __bfloat162float(__float2bfloat16_rn(a));
    float rb = b - __bfloat162float(__float2bfloat16_rn(b));
    __nv_bfloat162 h = __nv_bfloat162(__float2bfloat16_rn(ra), __float2bfloat16_rn(rb));
    return *(uint32_t*)&h;
}

// ---------------- split x + zero counters (one fused kernel) ----------------
__global__ void split_x_zero_kernel(const float* __restrict__ x,
                                    __nv_bfloat16* __restrict__ xhi,
                                    __nv_bfloat16* __restrict__ xlo,
                                    int* __restrict__ cnt0, int* __restrict__ cnt1) {
    long idx = (long)blockIdx.x * blockDim.x + threadIdx.x;
    if (idx < N_DST0) cnt0[idx] = 0;
    if (idx < N_DST1) cnt1[idx] = 0;
    long total = (long)N_DST0 * IN_F / 4;
    if (idx >= total) return;
    float4 v = *((const float4*)x + idx);
    *((uint2*)xhi + idx) = make_uint2(pack_hi(v.x, v.y), pack_hi(v.z, v.w));
    *((uint2*)xlo + idx) = make_uint2(pack_lo(v.x, v.y), pack_lo(v.z, v.w));
}

// ---------------- CSR build --------------------------------------------------
__global__ void count_kernel(const int* __restrict__ dst, int* __restrict__ cnt, int E) {
    int e = blockIdx.x * blockDim.x + threadIdx.x;
    if (e < E) atomicAdd(&cnt[dst[e]], 1);
}

// single-block shuffle-based exclusive scan
__global__ void scan_kernel(const int* __restrict__ cnt, int* __restrict__ rowptr,
                            int* __restrict__ cursor, int n) {
    __shared__ int wsum[32];
    __shared__ int carry_s;
    int tid = threadIdx.x;
    int w = tid >> 5, lane = tid & 31;
    if (tid == 0) carry_s = 0;
    __syncthreads();
    for (int base = 0; base < n; base += 1024) {
        int i = base + tid;
        int v = (i < n) ? cnt[i] : 0;
        int s = v;
#pragma unroll
        for (int off = 1; off < 32; off <<= 1) {
            int t = __shfl_up_sync(0xFFFFFFFFu, s, off);
            if (lane >= off) s += t;
        }
        if (lane == 31) wsum[w] = s;
        __syncthreads();
        if (w == 0) {
            int ws = wsum[lane];
            int si = ws;
#pragma unroll
            for (int off = 1; off < 32; off <<= 1) {
                int t = __shfl_up_sync(0xFFFFFFFFu, si, off);
                if (lane >= off) si += t;
            }
            wsum[lane] = si - ws;  // exclusive warp offset
        }
        __syncthreads();
        int excl = s - v + wsum[w] + carry_s;
        if (i < n) { rowptr[i] = excl; cursor[i] = excl; }
        __syncthreads();
        if (tid == 1023) carry_s = excl + v;
        __syncthreads();
    }
    if (threadIdx.x == 0) rowptr[n] = carry_s;
}

__global__ void fill_kernel(const int* __restrict__ src, const int* __restrict__ dst,
                            int* __restrict__ cursor, int* __restrict__ perm, int E) {
    int e = blockIdx.x * blockDim.x + threadIdx.x;
    if (e < E) {
        int pos = atomicAdd(&cursor[dst[e]], 1);
        perm[pos] = src[e];
    }
}

// ---------------- gather aggregation -> bf16 hi/lo (warp per dst row) -------
template <int F>
__global__ void aggregate_kernel(const float* __restrict__ feat,
                                 const int* __restrict__ rowptr,
                                 const int* __restrict__ perm,
                                 __nv_bfloat16* __restrict__ outhi,
                                 __nv_bfloat16* __restrict__ outlo, int n) {
    int w = (blockIdx.x * blockDim.x + threadIdx.x) >> 5;
    if (w >= n) return;
    int lane = threadIdx.x & 31;
    int beg = rowptr[w], end = rowptr[w + 1];
    constexpr int V = F / 128;
    float4 acc[V];
#pragma unroll
    for (int v = 0; v < V; v++) acc[v] = make_float4(0.f, 0.f, 0.f, 0.f);
    for (int e = beg; e < end; e++) {
        const float4* p = (const float4*)(feat + (size_t)perm[e] * F) + lane;
#pragma unroll
        for (int v = 0; v < V; v++) {
            float4 t = p[v * 32];
            acc[v].x += t.x; acc[v].y += t.y; acc[v].z += t.z; acc[v].w += t.w;
        }
    }
    float inv = 1.0f / (float)max(end - beg, 1);
    uint2* oh = (uint2*)(outhi + (size_t)w * F) + lane;
    uint2* ol = (uint2*)(outlo + (size_t)w * F) + lane;
#pragma unroll
    for (int v = 0; v < V; v++) {
        float a = acc[v].x * inv, b = acc[v].y * inv, c = acc[v].z * inv, d = acc[v].w * inv;
        oh[v * 32] = make_uint2(pack_hi(a, b), pack_hi(c, d));
        ol[v * 32] = make_uint2(pack_lo(a, b), pack_lo(c, d));
    }
}

// ---------------- weight transpose + split ----------------------------------
__global__ void transpose_split_kernel(const float* __restrict__ W0, const float* __restrict__ W1,
                                       int Khalf, int N, int Ktot,
                                       __nv_bfloat16* __restrict__ bhi,
                                       __nv_bfloat16* __restrict__ blo) {
    __shared__ float t[32][33];
    int k0 = blockIdx.x * 32, n0 = blockIdx.y * 32;
    int tx = threadIdx.x, ty = threadIdx.y;
#pragma unroll
    for (int j = 0; j < 32; j += 8) {
        int k = k0 + ty + j, n = n0 + tx;
        const float* W = (k < Khalf) ? (W0 + (size_t)k * N) : (W1 + (size_t)(k - Khalf) * N);
        t[ty + j][tx] = W[n];
    }
    __syncthreads();
#pragma unroll
    for (int j = 0; j < 32; j += 8) {
        int n = n0 + ty + j, k = k0 + tx;
        float f = t[tx][ty + j];
        __nv_bfloat16 h = __float2bfloat16_rn(f);
        float r = f - __bfloat162float(h);
        bhi[(size_t)n * Ktot + k] = h;
        blo[(size_t)n * Ktot + k] = __float2bfloat16_rn(r);
    }
}

// ---------------- warp-MMA primitives ----------------------------------------
__device__ __forceinline__ void ldsm_x4(uint32_t r[4], uint32_t addr) {
    asm volatile("ldmatrix.sync.aligned.m8n8.x4.shared.b16 {%0,%1,%2,%3}, [%4];"
                 : "=r"(r[0]), "=r"(r[1]), "=r"(r[2]), "=r"(r[3]) : "r"(addr));
}
__device__ __forceinline__ void mma_bf16(float c[4], const uint32_t a[4], const uint32_t b0,
                                         const uint32_t b1) {
    asm volatile("mma.sync.aligned.m16n8k16.row.col.f32.bf16.bf16.f32 "
                 "{%0,%1,%2,%3}, {%4,%5,%6,%7}, {%8,%9}, {%0,%1,%2,%3};"
                 : "+f"(c[0]), "+f"(c[1]), "+f"(c[2]), "+f"(c[3])
                 : "r"(a[0]), "r"(a[1]), "r"(a[2]), "r"(a[3]), "r"(b0), "r"(b1));
}

// ---------------------------------------------------------------------------
// GEMM (all-bf16 operands, cp.async double-buffered):
//   C[M, ldC](cols n0..n0+BN) = [A1|A2] @ Bt^T + bias (ReLU optional)
//   A1,A2: [*, Khalf] bf16 hi/lo.  Bt: [Ntot, Ktot] bf16 hi/lo (K-major).
//   If SPLIT_OUT: rows < Msplit also written as bf16 hi/lo to Chi/Clo.
// Row pitch in smem: 40 bf16 (80 B) -> conflict-free ldmatrix, cp.async 16B ok.
// ---------------------------------------------------------------------------
template <int BM, int BN, int WM, int WN, bool RELU, bool SPLIT_OUT>
__global__ __launch_bounds__(256, 1)
void gemm_mma(const __nv_bfloat16* __restrict__ A1hi, const __nv_bfloat16* __restrict__ A1lo,
              const __nv_bfloat16* __restrict__ A2hi, const __nv_bfloat16* __restrict__ A2lo,
              int Khalf,
              const __nv_bfloat16* __restrict__ Bhi, const __nv_bfloat16* __restrict__ Blo,
              int Ktot, const float* __restrict__ bias, float* __restrict__ C,
              int M, int ldC,
              __nv_bfloat16* __restrict__ Chi, __nv_bfloat16* __restrict__ Clo, int Msplit) {
    extern __shared__ char smem[];
    constexpr int AH_OFF = 0;
    constexpr int AL_OFF = BM * 80;
    constexpr int BH_OFF = 2 * BM * 80;
    constexpr int BL_OFF = 2 * BM * 80 + BN * 80;
    constexpr int STAGE  = (2 * BM + 2 * BN) * 80;

    const uint32_t sb = smem_u32(smem);
    const int tid = threadIdx.x;
    const int wid = tid >> 5;
    const int lane = tid & 31;
    const int m0 = blockIdx.y * BM;
    const int n0 = blockIdx.x * BN;

    const int wm0 = (wid >> 2) * WM;
    const int wn0 = (wid & 3) * WN;

    constexpr int MT = WM / 16;
    constexpr int NT = WN / 16;

    float acc[MT][WN / 8][4];
#pragma unroll
    for (int i = 0; i < MT; i++)
#pragma unroll
        for (int j = 0; j < WN / 8; j++)
#pragma unroll
            for (int q = 0; q < 4; q++) acc[i][j][q] = 0.0f;

    // per-thread ldmatrix offsets (within a stage)
    const uint32_t a_rel = ((wm0 + (lane & 15)) * 40 + (lane >> 4) * 8) * 2;
    const uint32_t b_rel = ((wn0 + (lane & 7) + ((lane >> 4) << 3)) * 40 +
                            (((lane >> 3) & 1) << 3)) * 2;

    const int nChunks = Ktot / 32;

    auto issue = [&](int c) {
        const int s = c & 1;
        const uint32_t st = sb + s * STAGE;
        const int kg = c * 32;
        const __nv_bfloat16* Ah = (kg < Khalf) ? A1hi : A2hi;
        const __nv_bfloat16* Al = (kg < Khalf) ? A1lo : A2lo;
        const int ka = (kg < Khalf) ? kg : (kg - Khalf);
#pragma unroll
        for (int i = 0; i < BM / 64; i++) {
            int f = tid + i * 256;
            int row = f >> 2, seg = f & 3;
            bool ok = (m0 + row) < M;
            const char* gh = (const char*)(Ah + (size_t)(m0 + row) * Khalf + ka) + seg * 16;
            const char* gl = (const char*)(Al + (size_t)(m0 + row) * Khalf + ka) + seg * 16;
            uint32_t off = (uint32_t)(row * 80 + seg * 16);
            cp16(st + AH_OFF + off, gh, ok);
            cp16(st + AL_OFF + off, gl, ok);
        }
#pragma unroll
        for (int i = 0; i < BN / 64; i++) {
            int f = tid + i * 256;
            int row = f >> 2, seg = f & 3;
            const char* gh = (const char*)(Bhi + (size_t)(n0 + row) * Ktot + kg) + seg * 16;
            const char* gl = (const char*)(Blo + (size_t)(n0 + row) * Ktot + kg) + seg * 16;
            uint32_t off = (uint32_t)(row * 80 + seg * 16);
            cp16(st + BH_OFF + off, gh, true);
            cp16(st + BL_OFF + off, gl, true);
        }
        CP_COMMIT();
    };

    issue(0);
    for (int c = 0; c < nChunks; c++) {
        if (c + 1 < nChunks) {
            issue(c + 1);
            asm volatile("cp.async.wait_group 1;" ::: "memory");
        } else {
            asm volatile("cp.async.wait_group 0;" ::: "memory");
        }
        __syncthreads();

        const uint32_t st = sb + (uint32_t)(c & 1) * STAGE;
        const uint32_t a_h = st + AH_OFF + a_rel;
        const uint32_t a_l = st + AL_OFF + a_rel;
        const uint32_t b_h = st + BH_OFF + b_rel;
        const uint32_t b_l = st + BL_OFF + b_rel;

#pragma unroll
        for (int ks = 0; ks < 2; ks++) {
            const uint32_t akoff = ks * 32;
            uint32_t ah[MT][4], al[MT][4], bh[NT][4];
#pragma unroll
            for (int mi = 0; mi < MT; mi++)
                ldsm_x4(ah[mi], a_h + mi * (16 * 80) + akoff);
#pragma unroll
            for (int nj = 0; nj < NT; nj++)
                ldsm_x4(bh[nj], b_h + nj * (16 * 80) + akoff);
#pragma unroll
            for (int mi = 0; mi < MT; mi++)
#pragma unroll
                for (int nj = 0; nj < NT; nj++) {
                    mma_bf16(acc[mi][2 * nj + 0], ah[mi], bh[nj][0], bh[nj][1]);
                    mma_bf16(acc[mi][2 * nj + 1], ah[mi], bh[nj][2], bh[nj][3]);
                }
#pragma unroll
            for (int mi = 0; mi < MT; mi++)
                ldsm_x4(al[mi], a_l + mi * (16 * 80) + akoff);
#pragma unroll
            for (int mi = 0; mi < MT; mi++)
#pragma unroll
                for (int nj = 0; nj < NT; nj++) {
                    mma_bf16(acc[mi][2 * nj + 0], al[mi], bh[nj][0], bh[nj][1]);
                    mma_bf16(acc[mi][2 * nj + 1], al[mi], bh[nj][2], bh[nj][3]);
                }
#pragma unroll
            for (int nj = 0; nj < NT; nj++) {
                uint32_t bl[4];
                ldsm_x4(bl, b_l + nj * (16 * 80) + akoff);
#pragma unroll
                for (int mi = 0; mi < MT; mi++) {
                    mma_bf16(acc[mi][2 * nj + 0], ah[mi], bl[0], bl[1]);
                    mma_bf16(acc[mi][2 * nj + 1], ah[mi], bl[2], bl[3]);
                }
            }
        }
        __syncthreads();
    }

    // ---- epilogue ----
#pragma unroll
    for (int mi = 0; mi < MT; mi++) {
#pragma unroll
        for (int nf = 0; nf < WN / 8; nf++) {
            int col = n0 + wn0 + nf * 8 + (lane & 3) * 2;
            float bx = bias[col], by = bias[col + 1];
            int r0 = m0 + wm0 + mi * 16 + (lane >> 2);
            float* c = acc[mi][nf];
            if (r0 < M) {
                float ox = c[0] + bx, oy = c[1] + by;
                if (RELU) { ox = fmaxf(ox, 0.f); oy = fmaxf(oy, 0.f); }
                *(float2*)(C + (size_t)r0 * ldC + col) = make_float2(ox, oy);
                if (SPLIT_OUT && r0 < Msplit) {
                    *(uint32_t*)(Chi + (size_t)r0 * ldC + col) = pack_hi(ox, oy);
                    *(uint32_t*)(Clo + (size_t)r0 * ldC + col) = pack_lo(ox, oy);
                }
            }
            int r1 = r0 + 8;
            if (r1 < M) {
                float ox = c[2] + bx, oy = c[3] + by;
                if (RELU) { ox = fmaxf(ox, 0.f); oy = fmaxf(oy, 0.f); }
                *(float2*)(C + (size_t)r1 * ldC + col) = make_float2(ox, oy);
                if (SPLIT_OUT && r1 < Msplit) {
                    *(uint32_t*)(Chi + (size_t)r1 * ldC + col) = pack_hi(ox, oy);
                    *(uint32_t*)(Clo + (size_t)r1 * ldC + col) = pack_lo(ox, oy);
                }
            }
        }
    }
}

#define GSMEM(BM, BN) (2 * (2 * (BM) + 2 * (BN)) * 80)

// ---------------------------------------------------------------------------
extern "C" void kernel_launch(void* const* d_in, const int* in_sizes, int n_in,
                              void* d_out, int out_size) {
    const float* x        = (const float*)d_in[0];
    const float* W_self1  = (const float*)d_in[1];
    const float* W_neigh1 = (const float*)d_in[2];
    const float* b1       = (const float*)d_in[3];
    const float* W_self2  = (const float*)d_in[4];
    const float* W_neigh2 = (const float*)d_in[5];
    const float* b2       = (const float*)d_in[6];
    const int* e0_src     = (const int*)d_in[7];
    const int* e0_dst     = (const int*)d_in[8];
    const int* e1_src     = (const int*)d_in[9];
    const int* e1_dst     = (const int*)d_in[10];
    float* out = (float*)d_out;

    float *h1;
    int *cnt0, *rowptr0, *cursor0, *perm0, *cnt1, *rowptr1, *cursor1, *perm1;
    __nv_bfloat16 *xsh, *xsl, *s1h, *s1l, *h1sh, *h1sl, *s2h, *s2l;
    __nv_bfloat16 *bt1h, *bt1l, *bt2h, *bt2l;
    cudaGetSymbolAddress((void**)&h1,   g_h1);
    cudaGetSymbolAddress((void**)&xsh,  g_xs_hi);
    cudaGetSymbolAddress((void**)&xsl,  g_xs_lo);
    cudaGetSymbolAddress((void**)&s1h,  g_s1_hi);
    cudaGetSymbolAddress((void**)&s1l,  g_s1_lo);
    cudaGetSymbolAddress((void**)&h1sh, g_h1s_hi);
    cudaGetSymbolAddress((void**)&h1sl, g_h1s_lo);
    cudaGetSymbolAddress((void**)&s2h,  g_s2_hi);
    cudaGetSymbolAddress((void**)&s2l,  g_s2_lo);
    cudaGetSymbolAddress((void**)&cnt0, g_cnt0);
    cudaGetSymbolAddress((void**)&rowptr0, g_rowptr0);
    cudaGetSymbolAddress((void**)&cursor0, g_cursor0);
    cudaGetSymbolAddress((void**)&perm0, g_perm0);
    cudaGetSymbolAddress((void**)&cnt1, g_cnt1);
    cudaGetSymbolAddress((void**)&rowptr1, g_rowptr1);
    cudaGetSymbolAddress((void**)&cursor1, g_cursor1);
    cudaGetSymbolAddress((void**)&perm1, g_perm1);
    cudaGetSymbolAddress((void**)&bt1h, g_bt1_hi);
    cudaGetSymbolAddress((void**)&bt1l, g_bt1_lo);
    cudaGetSymbolAddress((void**)&bt2h, g_bt2_hi);
    cudaGetSymbolAddress((void**)&bt2l, g_bt2_lo);

    cudaFuncSetAttribute((const void*)gemm_mma<128, 256, 64, 64, true, true>,
                         cudaFuncAttributeMaxDynamicSharedMemorySize, GSMEM(128, 256));
    cudaFuncSetAttribute((const void*)gemm_mma<64, 128, 32, 32, false, false>,
                         cudaFuncAttributeMaxDynamicSharedMemorySize, GSMEM(64, 128));

    // ---- layer 1 prep ----
    split_x_zero_kernel<<<(N_DST0 * IN_F / 4 + 255) / 256, 256>>>(x, xsh, xsl, cnt0, cnt1);
    count_kernel<<<(E0 + 255) / 256, 256>>>(e0_dst, cnt0, E0);
    scan_kernel<<<1, 1024>>>(cnt0, rowptr0, cursor0, N_DST0);
    fill_kernel<<<(E0 + 255) / 256, 256>>>(e0_src, e0_dst, cursor0, perm0, E0);
    {
        dim3 blk(32, 8);
        dim3 g1(2 * IN_F / 32, H_F / 32);
        transpose_split_kernel<<<g1, blk>>>(W_self1, W_neigh1, IN_F, H_F, 2 * IN_F, bt1h, bt1l);
    }
    aggregate_kernel<IN_F><<<(N_DST0 * 32 + 255) / 256, 256>>>(x, rowptr0, perm0, s1h, s1l, N_DST0);

    // ---- layer 1 GEMM: h1 = relu([x|sum1] @ Bt1^T + b1), split rows<5000 ----
    {
        dim3 grid(H_F / 256, (N_DST0 + 127) / 128);
        gemm_mma<128, 256, 64, 64, true, true><<<grid, 256, GSMEM(128, 256)>>>(
            xsh, xsl, s1h, s1l, IN_F, bt1h, bt1l, 2 * IN_F, b1, h1, N_DST0, H_F,
            h1sh, h1sl, N_DST1);
    }

    // ---- layer 2 ----
    count_kernel<<<(E1 + 255) / 256, 256>>>(e1_dst, cnt1, E1);
    scan_kernel<<<1, 1024>>>(cnt1, rowptr1, cursor1, N_DST1);
    fill_kernel<<<(E1 + 255) / 256, 256>>>(e1_src, e1_dst, cursor1, perm1, E1);
    {
        dim3 blk(32, 8);
        dim3 g2(2 * H_F / 32, N_CLS / 32);
        transpose_split_kernel<<<g2, blk>>>(W_self2, W_neigh2, H_F, N_CLS, 2 * H_F, bt2h, bt2l);
    }
    aggregate_kernel<H_F><<<(N_DST1 * 32 + 255) / 256, 256>>>(h1, rowptr1, perm1, s2h, s2l, N_DST1);

    // ---- layer 2 GEMM: out = [h1|sum2] @ Bt2^T + b2 ----
    {
        dim3 grid(N_CLS / 128, (N_DST1 + 63) / 64);
        gemm_mma<64, 128, 32, 32, false, false><<<grid, 256, GSMEM(64, 128)>>>(
            h1sh, h1sl, s2h, s2l, H_F, bt2h, bt2l, 2 * H_F, b2, out, N_DST1, N_CLS,
            nullptr, nullptr, 0);
    }
    (void)in_sizes; (void)n_in; (void)out_size;
}